// round 16
// baseline (speedup 1.0000x reference)
#include <cuda_runtime.h>
#include <cuda_bf16.h>
#include <cuda_fp16.h>

// ---------------------------------------------------------------------------
// StDimLocalLocalContrastModel, all GEMMs via fp16 asymmetric 2-MMA:
//   activations = fp16 hi/lo split (eff. 2^-22), weights/pos = single fp16.
//   Per-GEMM dropped-term err ~1.4e-4 rms (validated at 8.8e-5 on GEMM4 in R13).
//   P=64, B=1024, C=256, HID=512, M = B*P = 65536
// 3-stage cp.async, XOR swizzle, 2 CTAs/SM, 72 KB smem.
// ---------------------------------------------------------------------------

#define BM 128
#define BN 128
#define BKK 32
#define TILE_ELEMS 4096               // 128 rows x 32 elems (8 KB @2B)
#define NSTAGE 3
#define SMEM_BYTES (3 * NSTAGE * TILE_ELEMS * 2)   // 72 KB

// ---- scratch (device globals; allocation-free) ----
__device__ __half g_a_hi [16777216];  // [65536,256] anchor -> later pred (alias)
__device__ __half g_a_lo [16777216];
__device__ __half g_pos_h[16777216];  // [65536,256] positive (single)
__device__ __half g_hid_hi[33554432]; // [65536,512]
__device__ __half g_hid_lo[33554432];
__device__ __half g_ap_hi[16777216];  // [65536,256]
__device__ __half g_ap_lo[16777216];
__device__ __half g_w1_h[131072];     // [512,256]
__device__ __half g_w2_h[131072];     // [256,512]
__device__ __half g_ww_h[65536];      // [256,256]

// ---- PTX helpers ----
__device__ __forceinline__ void cp16(const void* src, void* dst) {
    unsigned d = (unsigned)__cvta_generic_to_shared(dst);
    asm volatile("cp.async.cg.shared.global [%0], [%1], 16;" :: "r"(d), "l"(src));
}
__device__ __forceinline__ void cp_commit() { asm volatile("cp.async.commit_group;"); }
template<int N> __device__ __forceinline__ void cp_wait() {
    asm volatile("cp.async.wait_group %0;" :: "n"(N));
}
__device__ __forceinline__ void ldsm4(unsigned* r, const void* p) {
    unsigned a = (unsigned)__cvta_generic_to_shared(p);
    asm volatile("ldmatrix.sync.aligned.m8n8.x4.shared.b16 {%0,%1,%2,%3}, [%4];"
        : "=r"(r[0]), "=r"(r[1]), "=r"(r[2]), "=r"(r[3]) : "r"(a));
}
__device__ __forceinline__ void mma_f16(float* d, const unsigned* a, const unsigned* b) {
    asm volatile(
        "mma.sync.aligned.m16n8k16.row.col.f32.f16.f16.f32 "
        "{%0,%1,%2,%3}, {%4,%5,%6,%7}, {%8,%9}, {%0,%1,%2,%3};"
        : "+f"(d[0]), "+f"(d[1]), "+f"(d[2]), "+f"(d[3])
        : "r"(a[0]), "r"(a[1]), "r"(a[2]), "r"(a[3]), "r"(b[0]), "r"(b[1]));
}

// swizzle within a 128x32 (2-byte elem) tile: chunk' = chunk ^ ((row>>1)&3)
__device__ __forceinline__ const __half* swz(const __half* tile, int row, int kcol) {
    return tile + row * 32 + ((((kcol >> 3)) ^ ((row >> 1) & 3)) << 3);
}

// ---------------------------------------------------------------------------
// hgemm: C[m,n] = sum_k A[m,k]*B[n,k], A = hi/lo fp16 (2 MMA), B = single fp16.
// MODE 0: fp32 out (batched via z)   MODE 1: relu(acc+bias)->hi/lo
// MODE 2: acc+bias+resid->hi/lo      MODE 3: plain->hi/lo
// CTA 128x128, 8 warps (2x4), warp tile 64x32, 3-stage, 2 CTAs/SM.
// ---------------------------------------------------------------------------
template<int MODE>
__global__ __launch_bounds__(256, 2)
void hgemm(const __half* __restrict__ Ahi, const __half* __restrict__ Alo, long As, long Ab,
           const __half* __restrict__ Bh_, long Bs, long Bb,
           int K,
           float* __restrict__ Cf, long Cs, long Cb,
           __half* __restrict__ Ohi, __half* __restrict__ Olo, long Os,
           const float* __restrict__ bias,
           const __half* __restrict__ Rhi, const __half* __restrict__ Rlo, long Rs)
{
    extern __shared__ __half smem[];
    __half* sAh = smem;
    __half* sAl = smem + NSTAGE * TILE_ELEMS;
    __half* sBh = smem + 2 * NSTAGE * TILE_ELEMS;

    const int tid = threadIdx.x;
    const int wid = tid >> 5;
    const int lane = tid & 31;
    const long z = blockIdx.z;

    const __half* gAh = Ahi + z * Ab + (long)blockIdx.y * BM * As;
    const __half* gAl = Alo + z * Ab + (long)blockIdx.y * BM * As;
    const __half* gBh = Bh_ + z * Bb + (long)blockIdx.x * BN * Bs;

    auto loadTile = [&](const __half* g, long stride, int k0, __half* dst) {
        #pragma unroll
        for (int it = 0; it < 2; it++) {
            int c = tid + it * 256;
            int r = c >> 2, kc = c & 3;
            cp16(g + (long)r * stride + k0 + kc * 8,
                 dst + r * 32 + ((kc ^ ((r >> 1) & 3)) << 3));
        }
    };
    auto loadAll = [&](int kt, int s) {
        int k0 = kt * BKK;
        loadTile(gAh, As, k0, sAh + s * TILE_ELEMS);
        loadTile(gAl, As, k0, sAl + s * TILE_ELEMS);
        loadTile(gBh, Bs, k0, sBh + s * TILE_ELEMS);
        cp_commit();
    };

    float acc[4][4][4];
    #pragma unroll
    for (int i = 0; i < 4; i++)
        #pragma unroll
        for (int j = 0; j < 4; j++)
            #pragma unroll
            for (int q = 0; q < 4; q++) acc[i][j][q] = 0.0f;

    const int wm = (wid >> 2) * 64;
    const int wn = (wid & 3) * 32;
    const int aRow = (lane & 7) + ((lane >> 3) & 1) * 8;
    const int aColH = ((lane >> 4) & 1) * 8;
    const int bRow = (lane & 7) + ((lane >> 4) & 1) * 8;
    const int bColH = ((lane >> 3) & 1) * 8;

    const int nk = K / BKK;
    loadAll(0, 0);
    loadAll(1, 1);

    for (int kt = 0; kt < nk; kt++) {
        if (kt + 1 < nk) cp_wait<1>(); else cp_wait<0>();
        __syncthreads();
        if (kt + 2 < nk) loadAll(kt + 2, (kt + 2) % NSTAGE);

        const int s = kt % NSTAGE;
        const __half* Ah = sAh + s * TILE_ELEMS;
        const __half* Al = sAl + s * TILE_ELEMS;
        const __half* Bh = sBh + s * TILE_ELEMS;

        #pragma unroll
        for (int kh = 0; kh < BKK; kh += 16) {
            unsigned Bh4[2][4];
            #pragma unroll
            for (int nj = 0; nj < 2; nj++)
                ldsm4(Bh4[nj], swz(Bh, wn + nj * 16 + bRow, kh + bColH));
            #pragma unroll
            for (int mi = 0; mi < 4; mi++) {
                unsigned Ah4[4], Al4[4];
                ldsm4(Ah4, swz(Ah, wm + mi * 16 + aRow, kh + aColH));
                ldsm4(Al4, swz(Al, wm + mi * 16 + aRow, kh + aColH));
                #pragma unroll
                for (int ni = 0; ni < 4; ni++) {
                    const unsigned* bh = &Bh4[ni >> 1][(ni & 1) * 2];
                    mma_f16(acc[mi][ni], Ah4, bh);   // hi*B
                    mma_f16(acc[mi][ni], Al4, bh);   // lo*B
                }
            }
        }
    }

    const int quad = lane >> 2, qt = lane & 3;
    const long rowBase = (long)blockIdx.y * BM + wm;
    const int colBase = blockIdx.x * BN + wn;

    #pragma unroll
    for (int mi = 0; mi < 4; mi++) {
        #pragma unroll
        for (int ni = 0; ni < 4; ni++) {
            #pragma unroll
            for (int half = 0; half < 2; half++) {
                long m = rowBase + mi * 16 + quad + half * 8;
                int n = colBase + ni * 8 + qt * 2;
                float v0 = acc[mi][ni][half * 2 + 0];
                float v1 = acc[mi][ni][half * 2 + 1];
                if (MODE == 0) {
                    *(float2*)(Cf + z * Cb + m * Cs + n) = make_float2(v0, v1);
                } else {
                    if (MODE == 1) {
                        v0 = fmaxf(v0 + bias[n], 0.0f);
                        v1 = fmaxf(v1 + bias[n + 1], 0.0f);
                    } else if (MODE == 2) {
                        __half2 rh = *(const __half2*)(Rhi + m * Rs + n);
                        __half2 rl = *(const __half2*)(Rlo + m * Rs + n);
                        v0 += bias[n]     + __half2float(rh.x) + __half2float(rl.x);
                        v1 += bias[n + 1] + __half2float(rh.y) + __half2float(rl.y);
                    }
                    __half h0 = __float2half(v0);
                    __half h1 = __float2half(v1);
                    __half l0 = __float2half(v0 - __half2float(h0));
                    __half l1 = __float2half(v1 - __half2float(h1));
                    *(__half2*)(Ohi + m * Os + n) = __halves2half2(h0, h1);
                    *(__half2*)(Olo + m * Os + n) = __halves2half2(l0, l1);
                }
            }
        }
    }
}

// ---------------------------------------------------------------------------
// prep: z=0 anchor -> fp16 hi/lo; z=1 positive -> fp16 single
// ---------------------------------------------------------------------------
__global__ void transpose_split(const float* __restrict__ in0, __half* __restrict__ h0, __half* __restrict__ l0,
                                const float* __restrict__ in1, __half* __restrict__ h1) {
    __shared__ float t[32][33];
    int zz = blockIdx.z;
    const float* in = zz ? in1 : in0;
    int b  = blockIdx.y;
    int c0 = (blockIdx.x & 7) * 32;
    int p0 = (blockIdx.x >> 3) * 32;
    const float* src = in + (long)b * 16384;
    #pragma unroll
    for (int j = 0; j < 32; j += 8)
        t[threadIdx.y + j][threadIdx.x] = src[(c0 + threadIdx.y + j) * 64 + p0 + threadIdx.x];
    __syncthreads();
    #pragma unroll
    for (int j = 0; j < 32; j += 8) {
        float v = t[threadIdx.x][threadIdx.y + j];
        long rowoff = ((long)b * 64 + p0 + threadIdx.y + j) * 256 + c0 + threadIdx.x;
        if (zz == 0) {
            __half h = __float2half(v);
            h0[rowoff] = h;
            l0[rowoff] = __float2half(v - __half2float(h));
        } else {
            h1[rowoff] = __float2half(v);
        }
    }
}

// weights -> single fp16: W1 (131072) | W2 (131072) | Ww (65536)
__global__ void cvt_w3(const float* __restrict__ W1, __half* __restrict__ w1,
                       const float* __restrict__ W2, __half* __restrict__ w2,
                       const float* __restrict__ Ww, __half* __restrict__ ww) {
    int i = blockIdx.x * 256 + threadIdx.x;
    if (i < 131072)      w1[i] = __float2half(W1[i]);
    else if (i < 262144) w2[i - 131072] = __float2half(W2[i - 131072]);
    else                 ww[i - 262144] = __float2half(Ww[i - 262144]);
}

// subtract row max in-place, row = 1024 floats
__global__ void rowmax_kernel(float* __restrict__ out) {
    long row = blockIdx.x;
    float4* rp = (float4*)(out + row * 1024);
    float4 v = rp[threadIdx.x];
    float m = fmaxf(fmaxf(v.x, v.y), fmaxf(v.z, v.w));
    #pragma unroll
    for (int o = 16; o; o >>= 1) m = fmaxf(m, __shfl_xor_sync(0xffffffffu, m, o));
    __shared__ float sm[8];
    if ((threadIdx.x & 31) == 0) sm[threadIdx.x >> 5] = m;
    __syncthreads();
    float mm = sm[0];
    #pragma unroll
    for (int i = 1; i < 8; i++) mm = fmaxf(mm, sm[i]);
    v.x -= mm; v.y -= mm; v.z -= mm; v.w -= mm;
    rp[threadIdx.x] = v;
}

extern "C" void kernel_launch(void* const* d_in, const int* in_sizes, int n_in,
                              void* d_out, int out_size) {
    const float* anchor   = (const float*)d_in[0];
    const float* positive = (const float*)d_in[1];
    const float* W1 = (const float*)d_in[2];
    const float* b1 = (const float*)d_in[3];
    const float* W2 = (const float*)d_in[4];
    const float* b2 = (const float*)d_in[5];
    const float* Ww = (const float*)d_in[6];
    float* out = (float*)d_out;

    __half *ah, *al, *posh, *hh, *hl, *aph, *apl, *w1, *w2, *ww;
    cudaGetSymbolAddress((void**)&ah,   g_a_hi);
    cudaGetSymbolAddress((void**)&al,   g_a_lo);
    cudaGetSymbolAddress((void**)&posh, g_pos_h);
    cudaGetSymbolAddress((void**)&hh,   g_hid_hi);
    cudaGetSymbolAddress((void**)&hl,   g_hid_lo);
    cudaGetSymbolAddress((void**)&aph,  g_ap_hi);
    cudaGetSymbolAddress((void**)&apl,  g_ap_lo);
    cudaGetSymbolAddress((void**)&w1,   g_w1_h);
    cudaGetSymbolAddress((void**)&w2,   g_w2_h);
    cudaGetSymbolAddress((void**)&ww,   g_ww_h);

    cudaFuncSetAttribute(hgemm<0>, cudaFuncAttributeMaxDynamicSharedMemorySize, SMEM_BYTES);
    cudaFuncSetAttribute(hgemm<1>, cudaFuncAttributeMaxDynamicSharedMemorySize, SMEM_BYTES);
    cudaFuncSetAttribute(hgemm<2>, cudaFuncAttributeMaxDynamicSharedMemorySize, SMEM_BYTES);
    cudaFuncSetAttribute(hgemm<3>, cudaFuncAttributeMaxDynamicSharedMemorySize, SMEM_BYTES);

    // prep
    transpose_split<<<dim3(16, 1024, 2), dim3(32, 8)>>>(anchor, ah, al, positive, posh);
    cvt_w3<<<1280, 256>>>(W1, w1, W2, w2, Ww, ww);

    // GEMM1: hidden = relu(a @ W1^T + b1)  [65536,512]
    hgemm<1><<<dim3(4, 512), 256, SMEM_BYTES>>>(
        ah, al, 256, 0, w1, 256, 0, 256,
        nullptr, 0, 0, hh, hl, 512, b1, nullptr, nullptr, 0);
    // GEMM2: aprime = a + hidden @ W2^T + b2  [65536,256]
    hgemm<2><<<dim3(2, 512), 256, SMEM_BYTES>>>(
        hh, hl, 512, 0, w2, 512, 0, 512,
        nullptr, 0, 0, aph, apl, 256, b2, ah, al, 256);
    // GEMM3: pred = aprime @ Ww^T -> hi/lo over dead anchor buffers
    hgemm<3><<<dim3(2, 512), 256, SMEM_BYTES>>>(
        aph, apl, 256, 0, ww, 256, 0, 256,
        nullptr, 0, 0, ah, al, 256, nullptr, nullptr, nullptr, 0);
    // GEMM4 (batched p=64): logits[p] = pred_p @ pos_p^T  [1024,1024]
    hgemm<0><<<dim3(8, 8, 64), 256, SMEM_BYTES>>>(
        ah, al, 16384, 256, posh, 16384, 256, 256,
        out, 1024, 1048576, nullptr, nullptr, 0, nullptr, nullptr, nullptr, 0);
    // subtract row max in-place
    rowmax_kernel<<<65536, 256>>>(out);
}

// round 17
// speedup vs baseline: 1.4673x; 1.4673x over previous
#include <cuda_runtime.h>
#include <cuda_bf16.h>
#include <cuda_fp16.h>

// ---------------------------------------------------------------------------
// StDimLocalLocalContrastModel, all GEMMs via fp16 asymmetric 2-MMA:
//   activations = fp16 hi/lo split (eff. 2^-22), weights/pos = single fp16.
//   Per-GEMM dropped-term err ~1.4e-4 rms (validated at 8.8e-5 on GEMM4 in R13).
//   P=64, B=1024, C=256, HID=512, M = B*P = 65536
// 3-stage cp.async, XOR swizzle, 2 CTAs/SM, 72 KB smem.
// ---------------------------------------------------------------------------

#define BM 128
#define BN 128
#define BKK 32
#define TILE_ELEMS 4096               // 128 rows x 32 elems (8 KB @2B)
#define NSTAGE 3
#define SMEM_BYTES (3 * NSTAGE * TILE_ELEMS * 2)   // 72 KB

// ---- scratch (device globals; allocation-free) ----
__device__ __half g_a_hi [16777216];  // [65536,256] anchor -> later pred (alias)
__device__ __half g_a_lo [16777216];
__device__ __half g_pos_h[16777216];  // [65536,256] positive (single)
__device__ __half g_hid_hi[33554432]; // [65536,512]
__device__ __half g_hid_lo[33554432];
__device__ __half g_ap_hi[16777216];  // [65536,256]
__device__ __half g_ap_lo[16777216];
__device__ __half g_w1_h[131072];     // [512,256]
__device__ __half g_w2_h[131072];     // [256,512]
__device__ __half g_ww_h[65536];      // [256,256]

// ---- PTX helpers ----
__device__ __forceinline__ void cp16(const void* src, void* dst) {
    unsigned d = (unsigned)__cvta_generic_to_shared(dst);
    asm volatile("cp.async.cg.shared.global [%0], [%1], 16;" :: "r"(d), "l"(src));
}
__device__ __forceinline__ void cp_commit() { asm volatile("cp.async.commit_group;"); }
template<int N> __device__ __forceinline__ void cp_wait() {
    asm volatile("cp.async.wait_group %0;" :: "n"(N));
}
__device__ __forceinline__ void ldsm4(unsigned* r, const void* p) {
    unsigned a = (unsigned)__cvta_generic_to_shared(p);
    asm volatile("ldmatrix.sync.aligned.m8n8.x4.shared.b16 {%0,%1,%2,%3}, [%4];"
        : "=r"(r[0]), "=r"(r[1]), "=r"(r[2]), "=r"(r[3]) : "r"(a));
}
__device__ __forceinline__ void mma_f16(float* d, const unsigned* a, const unsigned* b) {
    asm volatile(
        "mma.sync.aligned.m16n8k16.row.col.f32.f16.f16.f32 "
        "{%0,%1,%2,%3}, {%4,%5,%6,%7}, {%8,%9}, {%0,%1,%2,%3};"
        : "+f"(d[0]), "+f"(d[1]), "+f"(d[2]), "+f"(d[3])
        : "r"(a[0]), "r"(a[1]), "r"(a[2]), "r"(a[3]), "r"(b[0]), "r"(b[1]));
}

// swizzle within a 128x32 (2-byte elem) tile: chunk' = chunk ^ ((row>>1)&3)
__device__ __forceinline__ const __half* swz(const __half* tile, int row, int kcol) {
    return tile + row * 32 + ((((kcol >> 3)) ^ ((row >> 1) & 3)) << 3);
}

// ---------------------------------------------------------------------------
// hgemm: C[m,n] = sum_k A[m,k]*B[n,k], A = hi/lo fp16 (2 MMA), B = single fp16.
// MODE 0: fp32 out (batched via z)   MODE 1: relu(acc+bias)->hi/lo
// MODE 2: acc+bias+resid->hi/lo      MODE 3: plain->hi/lo
// CTA 128x128, 8 warps (2x4), warp tile 64x32, 3-stage, 2 CTAs/SM.
// ---------------------------------------------------------------------------
template<int MODE>
__global__ __launch_bounds__(256, 2)
void hgemm(const __half* __restrict__ Ahi, const __half* __restrict__ Alo, long As, long Ab,
           const __half* __restrict__ Bh_, long Bs, long Bb,
           int K,
           float* __restrict__ Cf, long Cs, long Cb,
           __half* __restrict__ Ohi, __half* __restrict__ Olo, long Os,
           const float* __restrict__ bias,
           const __half* __restrict__ Rhi, const __half* __restrict__ Rlo, long Rs)
{
    extern __shared__ __half smem[];
    __half* sAh = smem;
    __half* sAl = smem + NSTAGE * TILE_ELEMS;
    __half* sBh = smem + 2 * NSTAGE * TILE_ELEMS;

    const int tid = threadIdx.x;
    const int wid = tid >> 5;
    const int lane = tid & 31;
    const long z = blockIdx.z;

    const __half* gAh = Ahi + z * Ab + (long)blockIdx.y * BM * As;
    const __half* gAl = Alo + z * Ab + (long)blockIdx.y * BM * As;
    const __half* gBh = Bh_ + z * Bb + (long)blockIdx.x * BN * Bs;

    auto loadTile = [&](const __half* g, long stride, int k0, __half* dst) {
        #pragma unroll
        for (int it = 0; it < 2; it++) {
            int c = tid + it * 256;
            int r = c >> 2, kc = c & 3;
            cp16(g + (long)r * stride + k0 + kc * 8,
                 dst + r * 32 + ((kc ^ ((r >> 1) & 3)) << 3));
        }
    };
    auto loadAll = [&](int kt, int s) {
        int k0 = kt * BKK;
        loadTile(gAh, As, k0, sAh + s * TILE_ELEMS);
        loadTile(gAl, As, k0, sAl + s * TILE_ELEMS);
        loadTile(gBh, Bs, k0, sBh + s * TILE_ELEMS);
        cp_commit();
    };

    float acc[4][4][4];
    #pragma unroll
    for (int i = 0; i < 4; i++)
        #pragma unroll
        for (int j = 0; j < 4; j++)
            #pragma unroll
            for (int q = 0; q < 4; q++) acc[i][j][q] = 0.0f;

    const int wm = (wid >> 2) * 64;
    const int wn = (wid & 3) * 32;
    const int aRow = (lane & 7) + ((lane >> 3) & 1) * 8;
    const int aColH = ((lane >> 4) & 1) * 8;
    const int bRow = (lane & 7) + ((lane >> 4) & 1) * 8;
    const int bColH = ((lane >> 3) & 1) * 8;

    const int nk = K / BKK;
    loadAll(0, 0);
    loadAll(1, 1);

    for (int kt = 0; kt < nk; kt++) {
        if (kt + 1 < nk) cp_wait<1>(); else cp_wait<0>();
        __syncthreads();
        if (kt + 2 < nk) loadAll(kt + 2, (kt + 2) % NSTAGE);

        const int s = kt % NSTAGE;
        const __half* Ah = sAh + s * TILE_ELEMS;
        const __half* Al = sAl + s * TILE_ELEMS;
        const __half* Bh = sBh + s * TILE_ELEMS;

        #pragma unroll
        for (int kh = 0; kh < BKK; kh += 16) {
            unsigned Bh4[2][4];
            #pragma unroll
            for (int nj = 0; nj < 2; nj++)
                ldsm4(Bh4[nj], swz(Bh, wn + nj * 16 + bRow, kh + bColH));
            #pragma unroll
            for (int mi = 0; mi < 4; mi++) {
                unsigned Ah4[4], Al4[4];
                ldsm4(Ah4, swz(Ah, wm + mi * 16 + aRow, kh + aColH));
                ldsm4(Al4, swz(Al, wm + mi * 16 + aRow, kh + aColH));
                #pragma unroll
                for (int ni = 0; ni < 4; ni++) {
                    const unsigned* bh = &Bh4[ni >> 1][(ni & 1) * 2];
                    mma_f16(acc[mi][ni], Ah4, bh);   // hi*B
                    mma_f16(acc[mi][ni], Al4, bh);   // lo*B
                }
            }
        }
    }

    const int quad = lane >> 2, qt = lane & 3;
    const long rowBase = (long)blockIdx.y * BM + wm;
    const int colBase = blockIdx.x * BN + wn;

    #pragma unroll
    for (int mi = 0; mi < 4; mi++) {
        #pragma unroll
        for (int ni = 0; ni < 4; ni++) {
            #pragma unroll
            for (int half = 0; half < 2; half++) {
                long m = rowBase + mi * 16 + quad + half * 8;
                int n = colBase + ni * 8 + qt * 2;
                float v0 = acc[mi][ni][half * 2 + 0];
                float v1 = acc[mi][ni][half * 2 + 1];
                if (MODE == 0) {
                    *(float2*)(Cf + z * Cb + m * Cs + n) = make_float2(v0, v1);
                } else {
                    if (MODE == 1) {
                        v0 = fmaxf(v0 + bias[n], 0.0f);
                        v1 = fmaxf(v1 + bias[n + 1], 0.0f);
                    } else if (MODE == 2) {
                        __half2 rh = *(const __half2*)(Rhi + m * Rs + n);
                        __half2 rl = *(const __half2*)(Rlo + m * Rs + n);
                        v0 += bias[n]     + __half2float(rh.x) + __half2float(rl.x);
                        v1 += bias[n + 1] + __half2float(rh.y) + __half2float(rl.y);
                    }
                    __half h0 = __float2half(v0);
                    __half h1 = __float2half(v1);
                    __half l0 = __float2half(v0 - __half2float(h0));
                    __half l1 = __float2half(v1 - __half2float(h1));
                    *(__half2*)(Ohi + m * Os + n) = __halves2half2(h0, h1);
                    *(__half2*)(Olo + m * Os + n) = __halves2half2(l0, l1);
                }
            }
        }
    }
}

// ---------------------------------------------------------------------------
// prep: z=0 anchor -> fp16 hi/lo; z=1 positive -> fp16 single
// ---------------------------------------------------------------------------
__global__ void transpose_split(const float* __restrict__ in0, __half* __restrict__ h0, __half* __restrict__ l0,
                                const float* __restrict__ in1, __half* __restrict__ h1) {
    __shared__ float t[32][33];
    int zz = blockIdx.z;
    const float* in = zz ? in1 : in0;
    int b  = blockIdx.y;
    int c0 = (blockIdx.x & 7) * 32;
    int p0 = (blockIdx.x >> 3) * 32;
    const float* src = in + (long)b * 16384;
    #pragma unroll
    for (int j = 0; j < 32; j += 8)
        t[threadIdx.y + j][threadIdx.x] = src[(c0 + threadIdx.y + j) * 64 + p0 + threadIdx.x];
    __syncthreads();
    #pragma unroll
    for (int j = 0; j < 32; j += 8) {
        float v = t[threadIdx.x][threadIdx.y + j];
        long rowoff = ((long)b * 64 + p0 + threadIdx.y + j) * 256 + c0 + threadIdx.x;
        if (zz == 0) {
            __half h = __float2half(v);
            h0[rowoff] = h;
            l0[rowoff] = __float2half(v - __half2float(h));
        } else {
            h1[rowoff] = __float2half(v);
        }
    }
}

// weights -> single fp16: W1 (131072) | W2 (131072) | Ww (65536)
__global__ void cvt_w3(const float* __restrict__ W1, __half* __restrict__ w1,
                       const float* __restrict__ W2, __half* __restrict__ w2,
                       const float* __restrict__ Ww, __half* __restrict__ ww) {
    int i = blockIdx.x * 256 + threadIdx.x;
    if (i < 131072)      w1[i] = __float2half(W1[i]);
    else if (i < 262144) w2[i - 131072] = __float2half(W2[i - 131072]);
    else                 ww[i - 262144] = __float2half(Ww[i - 262144]);
}

// subtract row max in-place, row = 1024 floats
__global__ void rowmax_kernel(float* __restrict__ out) {
    long row = blockIdx.x;
    float4* rp = (float4*)(out + row * 1024);
    float4 v = rp[threadIdx.x];
    float m = fmaxf(fmaxf(v.x, v.y), fmaxf(v.z, v.w));
    #pragma unroll
    for (int o = 16; o; o >>= 1) m = fmaxf(m, __shfl_xor_sync(0xffffffffu, m, o));
    __shared__ float sm[8];
    if ((threadIdx.x & 31) == 0) sm[threadIdx.x >> 5] = m;
    __syncthreads();
    float mm = sm[0];
    #pragma unroll
    for (int i = 1; i < 8; i++) mm = fmaxf(mm, sm[i]);
    v.x -= mm; v.y -= mm; v.z -= mm; v.w -= mm;
    rp[threadIdx.x] = v;
}

extern "C" void kernel_launch(void* const* d_in, const int* in_sizes, int n_in,
                              void* d_out, int out_size) {
    const float* anchor   = (const float*)d_in[0];
    const float* positive = (const float*)d_in[1];
    const float* W1 = (const float*)d_in[2];
    const float* b1 = (const float*)d_in[3];
    const float* W2 = (const float*)d_in[4];
    const float* b2 = (const float*)d_in[5];
    const float* Ww = (const float*)d_in[6];
    float* out = (float*)d_out;

    __half *ah, *al, *posh, *hh, *hl, *aph, *apl, *w1, *w2, *ww;
    cudaGetSymbolAddress((void**)&ah,   g_a_hi);
    cudaGetSymbolAddress((void**)&al,   g_a_lo);
    cudaGetSymbolAddress((void**)&posh, g_pos_h);
    cudaGetSymbolAddress((void**)&hh,   g_hid_hi);
    cudaGetSymbolAddress((void**)&hl,   g_hid_lo);
    cudaGetSymbolAddress((void**)&aph,  g_ap_hi);
    cudaGetSymbolAddress((void**)&apl,  g_ap_lo);
    cudaGetSymbolAddress((void**)&w1,   g_w1_h);
    cudaGetSymbolAddress((void**)&w2,   g_w2_h);
    cudaGetSymbolAddress((void**)&ww,   g_ww_h);

    cudaFuncSetAttribute(hgemm<0>, cudaFuncAttributeMaxDynamicSharedMemorySize, SMEM_BYTES);
    cudaFuncSetAttribute(hgemm<1>, cudaFuncAttributeMaxDynamicSharedMemorySize, SMEM_BYTES);
    cudaFuncSetAttribute(hgemm<2>, cudaFuncAttributeMaxDynamicSharedMemorySize, SMEM_BYTES);
    cudaFuncSetAttribute(hgemm<3>, cudaFuncAttributeMaxDynamicSharedMemorySize, SMEM_BYTES);

    // prep
    transpose_split<<<dim3(16, 1024, 2), dim3(32, 8)>>>(anchor, ah, al, positive, posh);
    cvt_w3<<<1280, 256>>>(W1, w1, W2, w2, Ww, ww);

    // GEMM1: hidden = relu(a @ W1^T + b1)  [65536,512]
    hgemm<1><<<dim3(4, 512), 256, SMEM_BYTES>>>(
        ah, al, 256, 0, w1, 256, 0, 256,
        nullptr, 0, 0, hh, hl, 512, b1, nullptr, nullptr, 0);
    // GEMM2: aprime = a + hidden @ W2^T + b2  [65536,256]
    hgemm<2><<<dim3(2, 512), 256, SMEM_BYTES>>>(
        hh, hl, 512, 0, w2, 512, 0, 512,
        nullptr, 0, 0, aph, apl, 256, b2, ah, al, 256);
    // GEMM3: pred = aprime @ Ww^T -> hi/lo over dead anchor buffers
    hgemm<3><<<dim3(2, 512), 256, SMEM_BYTES>>>(
        aph, apl, 256, 0, ww, 256, 0, 256,
        nullptr, 0, 0, ah, al, 256, nullptr, nullptr, nullptr, 0);
    // GEMM4 (batched p=64): logits[p] = pred_p @ pos_p^T  [1024,1024]
    hgemm<0><<<dim3(8, 8, 64), 256, SMEM_BYTES>>>(
        ah, al, 16384, 256, posh, 16384, 256, 256,
        out, 1024, 1048576, nullptr, nullptr, 0, nullptr, nullptr, nullptr, 0);
    // subtract row max in-place
    rowmax_kernel<<<65536, 256>>>(out);
}